// round 16
// baseline (speedup 1.0000x reference)
#include <cuda_runtime.h>
#include <cstdint>
#include <math.h>

#define B_  16
#define C_  256
#define H_  160
#define W_  160
#define HW_ (H_*W_)
#define NEG_SLOPE 0.001f

// ---------------- scratch -----------------------------------------------
__device__ float g_avg[B_*HW_];
__device__ float g_max[B_*HW_];
__device__ float g_bm [B_*HW_];
__device__ float g_F  [B_*4*HW_];
__device__ float g_Cm [B_*HW_];
__device__ float g_S  [B_*H_*H_];
__device__ float g_E  [(size_t)B_*C_*HW_];   // ~419 MB

__device__ __forceinline__ float lrelu(float v) {
    return v > 0.0f ? v : NEG_SLOPE * v;
}

__device__ __forceinline__ void cp_async16(void* smem_dst, const void* gmem_src) {
    unsigned int s = (unsigned int)__cvta_generic_to_shared(smem_dst);
    asm volatile("cp.async.ca.shared.global [%0], [%1], 16;\n" :: "r"(s), "l"(gmem_src));
}
__device__ __forceinline__ void cp_commit() {
    asm volatile("cp.async.commit_group;\n");
}
template<int N>
__device__ __forceinline__ void cp_wait() {
    asm volatile("cp.async.wait_group %0;\n" :: "n"(N));
}

// fp32 bits fed directly as tf32 operands (HW truncates low mantissa bits)
__device__ __forceinline__ void mma_tf32(float& c0, float& c1, float& c2, float& c3,
                                         float a0, float a1, float a2, float a3,
                                         float b0, float b1) {
    asm volatile(
        "mma.sync.aligned.m16n8k8.row.col.f32.tf32.tf32.f32 "
        "{%0,%1,%2,%3}, {%4,%5,%6,%7}, {%8,%9}, {%0,%1,%2,%3};"
        : "+f"(c0), "+f"(c1), "+f"(c2), "+f"(c3)
        : "r"(__float_as_uint(a0)), "r"(__float_as_uint(a1)),
          "r"(__float_as_uint(a2)), "r"(__float_as_uint(a3)),
          "r"(__float_as_uint(b0)), "r"(__float_as_uint(b1)));
}

// ---------------- k1: channel mean/max + w_ab dot, float4 ----------------
__global__ void k1_reduce(const float* __restrict__ x,
                          const float* __restrict__ w_ab) {
    __shared__ float sw[C_];
    int tid = threadIdx.x;
    sw[tid] = w_ab[tid];
    __syncthreads();

    int p4 = blockIdx.x * 256 + tid;
    int b  = blockIdx.y;
    const float4* xp = (const float4*)(x + (size_t)b * C_ * HW_) + p4;

    float4 s = make_float4(0,0,0,0);
    float4 m = make_float4(-3.4e38f,-3.4e38f,-3.4e38f,-3.4e38f);
    float4 d = make_float4(0,0,0,0);
#pragma unroll 4
    for (int c = 0; c < C_; c++) {
        float4 v = xp[(size_t)c * (HW_/4)];
        float wc = sw[c];
        s.x += v.x; s.y += v.y; s.z += v.z; s.w += v.w;
        m.x = fmaxf(m.x, v.x); m.y = fmaxf(m.y, v.y);
        m.z = fmaxf(m.z, v.z); m.w = fmaxf(m.w, v.w);
        d.x = fmaf(wc, v.x, d.x); d.y = fmaf(wc, v.y, d.y);
        d.z = fmaf(wc, v.z, d.z); d.w = fmaf(wc, v.w, d.w);
    }
    int o = b * (HW_/4) + p4;
    const float inv = 1.0f / 256.0f;
    ((float4*)g_avg)[o] = make_float4(s.x*inv, s.y*inv, s.z*inv, s.w*inv);
    ((float4*)g_max)[o] = m;
    ((float4*)g_bm )[o] = make_float4(lrelu(d.x), lrelu(d.y), lrelu(d.z), lrelu(d.w));
}

// ---------------- k2: multi-scale convs -> F planes + Cm -----------------
__global__ void k2_convs(const float* __restrict__ w1,
                         const float* __restrict__ w3,
                         const float* __restrict__ w5,
                         const float* __restrict__ w7,
                         const float* __restrict__ w_fc) {
    const int b  = blockIdx.z;
    const int h0 = blockIdx.y * 32;
    const int w0 = blockIdx.x * 32;

    __shared__ float sA[38][39];
    __shared__ float sM[38][39];

    int tid = threadIdx.y * 32 + threadIdx.x;
    const float* avgb = g_avg + b * HW_;
    const float* maxb = g_max + b * HW_;

    for (int t = tid; t < 38 * 38; t += 1024) {
        int r = t / 38, c = t - r * 38;
        int hh = h0 + r - 3, ww = w0 + c - 3;
        bool in = (hh >= 0 && hh < H_ && ww >= 0 && ww < W_);
        sA[r][c] = in ? avgb[hh * W_ + ww] : 0.0f;
        sM[r][c] = in ? maxb[hh * W_ + ww] : 0.0f;
    }
    __syncthreads();

    int ty = threadIdx.y, tx = threadIdx.x;
    int cy = ty + 3, cx = tx + 3;

    float s1 = w1[0] * sA[cy][cx] + w1[1] * sM[cy][cx];

    float s3 = 0.0f;
#pragma unroll
    for (int kh = 0; kh < 3; kh++)
#pragma unroll
        for (int kw = 0; kw < 3; kw++) {
            s3 += w3[kh * 3 + kw]      * sA[cy + kh - 1][cx + kw - 1];
            s3 += w3[9 + kh * 3 + kw]  * sM[cy + kh - 1][cx + kw - 1];
        }

    float s5 = 0.0f;
#pragma unroll
    for (int kh = 0; kh < 5; kh++)
#pragma unroll
        for (int kw = 0; kw < 5; kw++) {
            s5 += w5[kh * 5 + kw]       * sA[cy + kh - 2][cx + kw - 2];
            s5 += w5[25 + kh * 5 + kw]  * sM[cy + kh - 2][cx + kw - 2];
        }

    float s7 = 0.0f;
#pragma unroll
    for (int kh = 0; kh < 7; kh++)
#pragma unroll
        for (int kw = 0; kw < 7; kw++) {
            s7 += w7[kh * 7 + kw]       * sA[cy + kh - 3][cx + kw - 3];
            s7 += w7[49 + kh * 7 + kw]  * sM[cy + kh - 3][cx + kw - 3];
        }

    s1 = lrelu(s1); s3 = lrelu(s3); s5 = lrelu(s5); s7 = lrelu(s7);

    int h = h0 + ty, w = w0 + tx;
    size_t base = (size_t)b * 4 * HW_ + h * W_ + w;
    g_F[base]           = s1;
    g_F[base + HW_]     = s3;
    g_F[base + 2 * HW_] = s5;
    g_F[base + 3 * HW_] = s7;

    g_Cm[b * HW_ + h * W_ + w] =
        lrelu(w_fc[0] * s1 + w_fc[1] * s3 + w_fc[2] * s5 + w_fc[3] * s7);
}

// ---------------- k3: attention scores + softmax (exact fp32) ------------
__global__ void k3_attn() {
    const int h = blockIdx.x;
    const int b = blockIdx.y;
    const int tid = threadIdx.x;

    __shared__ float sb2[W_];
    __shared__ float red[256];

    const float* bmrow = g_bm + b * HW_ + h * W_;
    if (tid < W_) sb2[tid] = bmrow[tid];
    __syncthreads();

    float acc = 0.0f;
    if (tid < H_) {
        const float* cm = g_Cm + b * HW_ + tid;
#pragma unroll 8
        for (int w = 0; w < W_; w++)
            acc = fmaf(sb2[w], cm[w * W_], acc);
    }

    red[tid] = (tid < H_) ? acc : -3.4e38f;
    __syncthreads();
    for (int s = 128; s > 0; s >>= 1) {
        if (tid < s) red[tid] = fmaxf(red[tid], red[tid + s]);
        __syncthreads();
    }
    float mx = red[0];
    __syncthreads();

    float e = (tid < H_) ? __expf(acc - mx) : 0.0f;
    red[tid] = e;
    __syncthreads();
    for (int s = 128; s > 0; s >>= 1) {
        if (tid < s) red[tid] += red[tid + s];
        __syncthreads();
    }
    if (tid < H_)
        g_S[((size_t)b * H_ + h) * H_ + tid] = e * (1.0f / red[0]);
}

// ---------------- k5: E_c = S_b @ D_c, TF32 MMA, S resident --------------
// K chunk 16; next chunk's F data prefetched into REGISTERS during MMA.
#define SA_P 164           // S pitch: 164%32=4 -> conflict-free fragments
#define SB_P 168           // D pitch: 168%32=8 -> conflict-free fragments
#define K5_SMEM ((H_*SA_P + 2*16*SB_P)*4)
__global__ void __launch_bounds__(256)
k5_E(const float* __restrict__ w_fd) {
    extern __shared__ float sm5[];
    float* sA = sm5;                   // [160][SA_P] : full S tile
    float* sB = sm5 + H_ * SA_P;       // [2][16][SB_P]

    const int c = blockIdx.x;
    const int b = blockIdx.y;

    const float f0 = w_fd[c * 4 + 0];
    const float f1 = w_fd[c * 4 + 1];
    const float f2 = w_fd[c * 4 + 2];
    const float f3 = w_fd[c * 4 + 3];

    const float* Sb = g_S + (size_t)b * H_ * H_;
    const float* F0 = g_F + (size_t)b * 4 * HW_;
    const float* F1 = F0 + HW_;
    const float* F2 = F0 + 2 * HW_;
    const float* F3 = F0 + 3 * HW_;

    const int tid  = threadIdx.x;
    const int wid  = tid >> 5;
    const int lane = tid & 31;
    const int qr   = lane >> 2;
    const int qc   = lane & 3;
    const int mw0  = (wid & 1) * 80;
    const int nw0  = (wid >> 1) * 40;

    // per-thread element coords for D staging (5 float2 per chunk of 16 k)
    int dk[5], dw[5];
#pragma unroll
    for (int j = 0; j < 5; j++) {
        int i2 = tid + j * 256;            // 1280 float2 per chunk
        dk[j] = i2 / 80;
        dw[j] = (i2 - dk[j] * 80) * 2;
    }

    // stage full S via cp.async: 160 rows x 40 16B units
    for (int t = tid; t < H_ * 40; t += 256) {
        int row = t / 40, seg = t - row * 40;
        cp_async16(sA + row * SA_P + seg * 4, Sb + row * H_ + seg * 4);
    }
    cp_commit();

    // build first D chunk (k 0..15) into buffer 0
    {
#pragma unroll
        for (int j = 0; j < 5; j++) {
            int row = dk[j] * W_ + dw[j];
            float2 a0 = *(const float2*)&F0[row];
            float2 a1 = *(const float2*)&F1[row];
            float2 a2 = *(const float2*)&F2[row];
            float2 a3 = *(const float2*)&F3[row];
            float2 r;
            r.x = lrelu(f0*a0.x + f1*a1.x + f2*a2.x + f3*a3.x);
            r.y = lrelu(f0*a0.y + f1*a1.y + f2*a2.y + f3*a3.y);
            *(float2*)&sB[dk[j] * SB_P + dw[j]] = r;
        }
    }
    cp_wait<0>();
    __syncthreads();

    float acc[5][5][4];
#pragma unroll
    for (int i = 0; i < 5; i++)
#pragma unroll
        for (int j = 0; j < 5; j++)
#pragma unroll
            for (int q = 0; q < 4; q++) acc[i][j][q] = 0.0f;

    int buf = 0;
    for (int it = 0; it < 10; it++) {
        const int kc = it * 16;
        const float* bcur = sB + buf * 16 * SB_P;

        // prefetch next chunk's F data into registers (overlaps the MMAs)
        float2 p0[5], p1[5], p2[5], p3[5];
        if (it < 9) {
            const int kn = kc + 16;
#pragma unroll
            for (int j = 0; j < 5; j++) {
                int row = (kn + dk[j]) * W_ + dw[j];
                p0[j] = *(const float2*)&F0[row];
                p1[j] = *(const float2*)&F1[row];
                p2[j] = *(const float2*)&F2[row];
                p3[j] = *(const float2*)&F3[row];
            }
        }

#pragma unroll
        for (int kk = 0; kk < 16; kk += 8) {
            float Af[5][4];
#pragma unroll
            for (int mi = 0; mi < 5; mi++) {
                int m0 = mw0 + mi * 16;
                const float* ar = sA + kc + kk + qc;
                Af[mi][0] = ar[(m0 + qr)     * SA_P];
                Af[mi][1] = ar[(m0 + qr + 8) * SA_P];
                Af[mi][2] = ar[(m0 + qr)     * SA_P + 4];
                Af[mi][3] = ar[(m0 + qr + 8) * SA_P + 4];
            }
#pragma unroll
            for (int ni = 0; ni < 5; ni++) {
                int n0 = nw0 + ni * 8;
                float b0 = bcur[(kk + qc)     * SB_P + n0 + qr];
                float b1 = bcur[(kk + qc + 4) * SB_P + n0 + qr];
#pragma unroll
                for (int mi = 0; mi < 5; mi++)
                    mma_tf32(acc[mi][ni][0], acc[mi][ni][1],
                             acc[mi][ni][2], acc[mi][ni][3],
                             Af[mi][0], Af[mi][1], Af[mi][2], Af[mi][3],
                             b0, b1);
            }
        }

        if (it < 9) {                         // convert prefetched F -> D
            float* dst = sB + (buf ^ 1) * 16 * SB_P;
#pragma unroll
            for (int j = 0; j < 5; j++) {
                float2 r;
                r.x = lrelu(f0*p0[j].x + f1*p1[j].x + f2*p2[j].x + f3*p3[j].x);
                r.y = lrelu(f0*p0[j].y + f1*p1[j].y + f2*p2[j].y + f3*p3[j].y);
                *(float2*)&dst[dk[j] * SB_P + dw[j]] = r;
            }
        }
        __syncthreads();
        buf ^= 1;
    }

    float* Eb = g_E + ((size_t)(b * C_ + c)) * HW_;
#pragma unroll
    for (int mi = 0; mi < 5; mi++) {
        int r0 = mw0 + mi * 16 + qr;
#pragma unroll
        for (int ni = 0; ni < 5; ni++) {
            int col = nw0 + ni * 8 + 2 * qc;
            *(float2*)&Eb[r0 * W_ + col]       = make_float2(acc[mi][ni][0], acc[mi][ni][1]);
            *(float2*)&Eb[(r0 + 8) * W_ + col] = make_float2(acc[mi][ni][2], acc[mi][ni][3]);
        }
    }
}

// ---------------- k6: out = W_e @ E + x, TF32 MMA, both streamed ----------
// tile 128(o) x 64(p); 8 warps 4x2; warp 32x32; K chunk 16; 3-stage ring;
// ONE barrier per iteration; small footprint -> 3 CTAs/SM.
#define WP6 20             // sW pitch [128][20]: bank(20*qr+qc) all distinct
#define EP6 72             // sE pitch [16][72]:  72%32=8 -> conflict-free
#define K6_STG ((128*WP6 + 16*EP6))
#define K6_SMEM (3*K6_STG*4)
__global__ void __launch_bounds__(256, 3)
k6_out(const float* __restrict__ w_e,
       const float* __restrict__ x,
       float* __restrict__ out) {
    extern __shared__ float sm6[];

    const int pb = blockIdx.x;     // 0..399
    const int ob = blockIdx.y;     // 0..1
    const int b  = blockIdx.z;

    const int tid  = threadIdx.x;
    const int wid  = tid >> 5;
    const int lane = tid & 31;
    const int qr   = lane >> 2;
    const int qc   = lane & 3;
    const int mw0  = (wid & 3) * 32;     // warp M offset (o), 4 warps
    const int nw0  = (wid >> 2) * 32;    // warp N offset (p), 2 warps
    const int o0   = ob * 128;
    const int p0   = pb * 64;

    const float* Eb = g_E + (size_t)b * C_ * HW_ + p0;

    // stage chunk `ck` into ring slot `s`
    auto stage = [&](int s, int ck) {
        float* dW = sm6 + s * K6_STG;
        float* dE = dW + 128 * WP6;
        const int kc = ck * 16;
        // W: 128 rows x 4 16B units
        for (int t = tid; t < 512; t += 256) {
            int row = t >> 2, seg = t & 3;
            cp_async16(dW + row * WP6 + seg * 4,
                       w_e + (o0 + row) * C_ + kc + seg * 4);
        }
        // E: 16 rows x 16 16B units (256 total, one per thread)
        {
            int row = tid >> 4, seg = tid & 15;
            cp_async16(dE + row * EP6 + seg * 4,
                       Eb + (size_t)(kc + row) * HW_ + seg * 4);
        }
        cp_commit();
    };

    stage(0, 0);
    stage(1, 1);

    float acc[2][4][4];
#pragma unroll
    for (int i = 0; i < 2; i++)
#pragma unroll
        for (int j = 0; j < 4; j++)
#pragma unroll
            for (int q = 0; q < 4; q++) acc[i][j][q] = 0.0f;

    for (int it = 0; it < 16; it++) {
        if (it < 15) cp_wait<1>();   // chunk `it` landed; it+1 may be in flight
        else         cp_wait<0>();
        __syncthreads();             // data visible; prev compute on slot done
        if (it < 14) stage((it + 2) % 3, it + 2);

        const float* sW = sm6 + (it % 3) * K6_STG;
        const float* sE = sW + 128 * WP6;

#pragma unroll
        for (int kk = 0; kk < 16; kk += 8) {
            float Af[2][4];
#pragma unroll
            for (int mi = 0; mi < 2; mi++) {
                int m0 = mw0 + mi * 16;
                const float* ar = sW + kk + qc;
                Af[mi][0] = ar[(m0 + qr)     * WP6];
                Af[mi][1] = ar[(m0 + qr + 8) * WP6];
                Af[mi][2] = ar[(m0 + qr)     * WP6 + 4];
                Af[mi][3] = ar[(m0 + qr + 8) * WP6 + 4];
            }
#pragma unroll
            for (int ni = 0; ni < 4; ni++) {
                int n0 = nw0 + ni * 8;
                float b0 = sE[(kk + qc)     * EP6 + n0 + qr];
                float b1 = sE[(kk + qc + 4) * EP6 + n0 + qr];
#pragma unroll
                for (int mi = 0; mi < 2; mi++)
                    mma_tf32(acc[mi][ni][0], acc[mi][ni][1],
                             acc[mi][ni][2], acc[mi][ni][3],
                             Af[mi][0], Af[mi][1], Af[mi][2], Af[mi][3],
                             b0, b1);
            }
        }
    }

    const float* xb  = x   + (size_t)b * C_ * HW_ + p0;
    float*       obp = out + (size_t)b * C_ * HW_ + p0;
#pragma unroll
    for (int mi = 0; mi < 2; mi++) {
        int o = o0 + mw0 + mi * 16 + qr;
#pragma unroll
        for (int ni = 0; ni < 4; ni++) {
            int col = nw0 + ni * 8 + 2 * qc;
            {
                float2 xv = *(const float2*)&xb[(size_t)o * HW_ + col];
                *(float2*)&obp[(size_t)o * HW_ + col] =
                    make_float2(acc[mi][ni][0] + xv.x, acc[mi][ni][1] + xv.y);
            }
            {
                float2 xv = *(const float2*)&xb[(size_t)(o + 8) * HW_ + col];
                *(float2*)&obp[(size_t)(o + 8) * HW_ + col] =
                    make_float2(acc[mi][ni][2] + xv.x, acc[mi][ni][3] + xv.y);
            }
        }
    }
}

// ---------------- launch --------------------------------------------------
extern "C" void kernel_launch(void* const* d_in, const int* in_sizes, int n_in,
                              void* d_out, int out_size) {
    const float* x    = (const float*)d_in[0];
    const float* w1   = (const float*)d_in[1];
    const float* w3   = (const float*)d_in[2];
    const float* w5   = (const float*)d_in[3];
    const float* w7   = (const float*)d_in[4];
    const float* w_ab = (const float*)d_in[5];
    const float* w_fc = (const float*)d_in[6];
    const float* w_fd = (const float*)d_in[7];
    const float* w_e  = (const float*)d_in[8];
    float* out = (float*)d_out;

    cudaFuncSetAttribute(k5_E,   cudaFuncAttributeMaxDynamicSharedMemorySize, K5_SMEM);
    cudaFuncSetAttribute(k6_out, cudaFuncAttributeMaxDynamicSharedMemorySize, K6_SMEM);

    k1_reduce<<<dim3(HW_ / 1024, B_), 256>>>(x, w_ab);
    k2_convs <<<dim3(5, 5, B_), dim3(32, 32)>>>(w1, w3, w5, w7, w_fc);
    k3_attn  <<<dim3(H_, B_), 256>>>();
    k5_E     <<<dim3(C_, B_), 256, K5_SMEM>>>(w_fd);
    k6_out   <<<dim3(400, 2, B_), 256, K6_SMEM>>>(w_e, x, out);
}

// round 17
// speedup vs baseline: 1.1126x; 1.1126x over previous
#include <cuda_runtime.h>
#include <cstdint>
#include <math.h>

#define B_  16
#define C_  256
#define H_  160
#define W_  160
#define HW_ (H_*W_)
#define NEG_SLOPE 0.001f

// ---------------- scratch -----------------------------------------------
__device__ float g_avg[B_*HW_];
__device__ float g_max[B_*HW_];
__device__ float g_bm [B_*HW_];
__device__ float g_F  [B_*4*HW_];
__device__ float g_Cm [B_*HW_];
__device__ float g_S  [B_*H_*H_];
__device__ float g_E  [(size_t)B_*C_*HW_];   // ~419 MB

__device__ __forceinline__ float lrelu(float v) {
    return v > 0.0f ? v : NEG_SLOPE * v;
}

__device__ __forceinline__ void cp_async16(void* smem_dst, const void* gmem_src) {
    unsigned int s = (unsigned int)__cvta_generic_to_shared(smem_dst);
    asm volatile("cp.async.ca.shared.global [%0], [%1], 16;\n" :: "r"(s), "l"(gmem_src));
}
__device__ __forceinline__ void cp_commit() {
    asm volatile("cp.async.commit_group;\n");
}
template<int N>
__device__ __forceinline__ void cp_wait() {
    asm volatile("cp.async.wait_group %0;\n" :: "n"(N));
}

// fp32 bits fed directly as tf32 operands (HW truncates low mantissa bits)
__device__ __forceinline__ void mma_tf32(float& c0, float& c1, float& c2, float& c3,
                                         float a0, float a1, float a2, float a3,
                                         float b0, float b1) {
    asm volatile(
        "mma.sync.aligned.m16n8k8.row.col.f32.tf32.tf32.f32 "
        "{%0,%1,%2,%3}, {%4,%5,%6,%7}, {%8,%9}, {%0,%1,%2,%3};"
        : "+f"(c0), "+f"(c1), "+f"(c2), "+f"(c3)
        : "r"(__float_as_uint(a0)), "r"(__float_as_uint(a1)),
          "r"(__float_as_uint(a2)), "r"(__float_as_uint(a3)),
          "r"(__float_as_uint(b0)), "r"(__float_as_uint(b1)));
}

// ---------------- k1: channel mean/max + w_ab dot, float4 ----------------
__global__ void k1_reduce(const float* __restrict__ x,
                          const float* __restrict__ w_ab) {
    __shared__ float sw[C_];
    int tid = threadIdx.x;
    sw[tid] = w_ab[tid];
    __syncthreads();

    int p4 = blockIdx.x * 256 + tid;
    int b  = blockIdx.y;
    const float4* xp = (const float4*)(x + (size_t)b * C_ * HW_) + p4;

    float4 s = make_float4(0,0,0,0);
    float4 m = make_float4(-3.4e38f,-3.4e38f,-3.4e38f,-3.4e38f);
    float4 d = make_float4(0,0,0,0);
#pragma unroll 8
    for (int c = 0; c < C_; c++) {
        float4 v = xp[(size_t)c * (HW_/4)];
        float wc = sw[c];
        s.x += v.x; s.y += v.y; s.z += v.z; s.w += v.w;
        m.x = fmaxf(m.x, v.x); m.y = fmaxf(m.y, v.y);
        m.z = fmaxf(m.z, v.z); m.w = fmaxf(m.w, v.w);
        d.x = fmaf(wc, v.x, d.x); d.y = fmaf(wc, v.y, d.y);
        d.z = fmaf(wc, v.z, d.z); d.w = fmaf(wc, v.w, d.w);
    }
    int o = b * (HW_/4) + p4;
    const float inv = 1.0f / 256.0f;
    ((float4*)g_avg)[o] = make_float4(s.x*inv, s.y*inv, s.z*inv, s.w*inv);
    ((float4*)g_max)[o] = m;
    ((float4*)g_bm )[o] = make_float4(lrelu(d.x), lrelu(d.y), lrelu(d.z), lrelu(d.w));
}

// ---------------- k2: multi-scale convs -> F planes + Cm -----------------
__global__ void k2_convs(const float* __restrict__ w1,
                         const float* __restrict__ w3,
                         const float* __restrict__ w5,
                         const float* __restrict__ w7,
                         const float* __restrict__ w_fc) {
    const int b  = blockIdx.z;
    const int h0 = blockIdx.y * 32;
    const int w0 = blockIdx.x * 32;

    __shared__ float sA[38][39];
    __shared__ float sM[38][39];

    int tid = threadIdx.y * 32 + threadIdx.x;
    const float* avgb = g_avg + b * HW_;
    const float* maxb = g_max + b * HW_;

    for (int t = tid; t < 38 * 38; t += 1024) {
        int r = t / 38, c = t - r * 38;
        int hh = h0 + r - 3, ww = w0 + c - 3;
        bool in = (hh >= 0 && hh < H_ && ww >= 0 && ww < W_);
        sA[r][c] = in ? avgb[hh * W_ + ww] : 0.0f;
        sM[r][c] = in ? maxb[hh * W_ + ww] : 0.0f;
    }
    __syncthreads();

    int ty = threadIdx.y, tx = threadIdx.x;
    int cy = ty + 3, cx = tx + 3;

    float s1 = w1[0] * sA[cy][cx] + w1[1] * sM[cy][cx];

    float s3 = 0.0f;
#pragma unroll
    for (int kh = 0; kh < 3; kh++)
#pragma unroll
        for (int kw = 0; kw < 3; kw++) {
            s3 += w3[kh * 3 + kw]      * sA[cy + kh - 1][cx + kw - 1];
            s3 += w3[9 + kh * 3 + kw]  * sM[cy + kh - 1][cx + kw - 1];
        }

    float s5 = 0.0f;
#pragma unroll
    for (int kh = 0; kh < 5; kh++)
#pragma unroll
        for (int kw = 0; kw < 5; kw++) {
            s5 += w5[kh * 5 + kw]       * sA[cy + kh - 2][cx + kw - 2];
            s5 += w5[25 + kh * 5 + kw]  * sM[cy + kh - 2][cx + kw - 2];
        }

    float s7 = 0.0f;
#pragma unroll
    for (int kh = 0; kh < 7; kh++)
#pragma unroll
        for (int kw = 0; kw < 7; kw++) {
            s7 += w7[kh * 7 + kw]       * sA[cy + kh - 3][cx + kw - 3];
            s7 += w7[49 + kh * 7 + kw]  * sM[cy + kh - 3][cx + kw - 3];
        }

    s1 = lrelu(s1); s3 = lrelu(s3); s5 = lrelu(s5); s7 = lrelu(s7);

    int h = h0 + ty, w = w0 + tx;
    size_t base = (size_t)b * 4 * HW_ + h * W_ + w;
    g_F[base]           = s1;
    g_F[base + HW_]     = s3;
    g_F[base + 2 * HW_] = s5;
    g_F[base + 3 * HW_] = s7;

    g_Cm[b * HW_ + h * W_ + w] =
        lrelu(w_fc[0] * s1 + w_fc[1] * s3 + w_fc[2] * s5 + w_fc[3] * s7);
}

// ---------------- k3: attention scores + softmax (exact fp32) ------------
__global__ void k3_attn() {
    const int h = blockIdx.x;
    const int b = blockIdx.y;
    const int tid = threadIdx.x;

    __shared__ float sb2[W_];
    __shared__ float red[256];

    const float* bmrow = g_bm + b * HW_ + h * W_;
    if (tid < W_) sb2[tid] = bmrow[tid];
    __syncthreads();

    float acc = 0.0f;
    if (tid < H_) {
        const float* cm = g_Cm + b * HW_ + tid;
#pragma unroll 8
        for (int w = 0; w < W_; w++)
            acc = fmaf(sb2[w], cm[w * W_], acc);
    }

    red[tid] = (tid < H_) ? acc : -3.4e38f;
    __syncthreads();
    for (int s = 128; s > 0; s >>= 1) {
        if (tid < s) red[tid] = fmaxf(red[tid], red[tid + s]);
        __syncthreads();
    }
    float mx = red[0];
    __syncthreads();

    float e = (tid < H_) ? __expf(acc - mx) : 0.0f;
    red[tid] = e;
    __syncthreads();
    for (int s = 128; s > 0; s >>= 1) {
        if (tid < s) red[tid] += red[tid + s];
        __syncthreads();
    }
    if (tid < H_)
        g_S[((size_t)b * H_ + h) * H_ + tid] = e * (1.0f / red[0]);
}

// ---------------- k5: E_c = S_b @ D_c, TF32 MMA, S resident --------------
// K chunk 16; next chunk's F data prefetched into REGISTERS during MMA.
#define SA_P 164           // S pitch: 164%32=4 -> conflict-free fragments
#define SB_P 168           // D pitch: 168%32=8 -> conflict-free fragments
#define K5_SMEM ((H_*SA_P + 2*16*SB_P)*4)
__global__ void __launch_bounds__(256)
k5_E(const float* __restrict__ w_fd) {
    extern __shared__ float sm5[];
    float* sA = sm5;                   // [160][SA_P] : full S tile
    float* sB = sm5 + H_ * SA_P;       // [2][16][SB_P]

    const int c = blockIdx.x;
    const int b = blockIdx.y;

    const float f0 = w_fd[c * 4 + 0];
    const float f1 = w_fd[c * 4 + 1];
    const float f2 = w_fd[c * 4 + 2];
    const float f3 = w_fd[c * 4 + 3];

    const float* Sb = g_S + (size_t)b * H_ * H_;
    const float* F0 = g_F + (size_t)b * 4 * HW_;
    const float* F1 = F0 + HW_;
    const float* F2 = F0 + 2 * HW_;
    const float* F3 = F0 + 3 * HW_;

    const int tid  = threadIdx.x;
    const int wid  = tid >> 5;
    const int lane = tid & 31;
    const int qr   = lane >> 2;
    const int qc   = lane & 3;
    const int mw0  = (wid & 1) * 80;
    const int nw0  = (wid >> 1) * 40;

    // per-thread element coords for D staging (5 float2 per chunk of 16 k)
    int dk[5], dw[5];
#pragma unroll
    for (int j = 0; j < 5; j++) {
        int i2 = tid + j * 256;            // 1280 float2 per chunk
        dk[j] = i2 / 80;
        dw[j] = (i2 - dk[j] * 80) * 2;
    }

    // stage full S via cp.async: 160 rows x 40 16B units
    for (int t = tid; t < H_ * 40; t += 256) {
        int row = t / 40, seg = t - row * 40;
        cp_async16(sA + row * SA_P + seg * 4, Sb + row * H_ + seg * 4);
    }
    cp_commit();

    // build first D chunk (k 0..15) into buffer 0
    {
#pragma unroll
        for (int j = 0; j < 5; j++) {
            int row = dk[j] * W_ + dw[j];
            float2 a0 = *(const float2*)&F0[row];
            float2 a1 = *(const float2*)&F1[row];
            float2 a2 = *(const float2*)&F2[row];
            float2 a3 = *(const float2*)&F3[row];
            float2 r;
            r.x = lrelu(f0*a0.x + f1*a1.x + f2*a2.x + f3*a3.x);
            r.y = lrelu(f0*a0.y + f1*a1.y + f2*a2.y + f3*a3.y);
            *(float2*)&sB[dk[j] * SB_P + dw[j]] = r;
        }
    }
    cp_wait<0>();
    __syncthreads();

    float acc[5][5][4];
#pragma unroll
    for (int i = 0; i < 5; i++)
#pragma unroll
        for (int j = 0; j < 5; j++)
#pragma unroll
            for (int q = 0; q < 4; q++) acc[i][j][q] = 0.0f;

    int buf = 0;
    for (int it = 0; it < 10; it++) {
        const int kc = it * 16;
        const float* bcur = sB + buf * 16 * SB_P;

        // prefetch next chunk's F data into registers (overlaps the MMAs)
        float2 p0[5], p1[5], p2[5], p3[5];
        if (it < 9) {
            const int kn = kc + 16;
#pragma unroll
            for (int j = 0; j < 5; j++) {
                int row = (kn + dk[j]) * W_ + dw[j];
                p0[j] = *(const float2*)&F0[row];
                p1[j] = *(const float2*)&F1[row];
                p2[j] = *(const float2*)&F2[row];
                p3[j] = *(const float2*)&F3[row];
            }
        }

#pragma unroll
        for (int kk = 0; kk < 16; kk += 8) {
            float Af[5][4];
#pragma unroll
            for (int mi = 0; mi < 5; mi++) {
                int m0 = mw0 + mi * 16;
                const float* ar = sA + kc + kk + qc;
                Af[mi][0] = ar[(m0 + qr)     * SA_P];
                Af[mi][1] = ar[(m0 + qr + 8) * SA_P];
                Af[mi][2] = ar[(m0 + qr)     * SA_P + 4];
                Af[mi][3] = ar[(m0 + qr + 8) * SA_P + 4];
            }
#pragma unroll
            for (int ni = 0; ni < 5; ni++) {
                int n0 = nw0 + ni * 8;
                float b0 = bcur[(kk + qc)     * SB_P + n0 + qr];
                float b1 = bcur[(kk + qc + 4) * SB_P + n0 + qr];
#pragma unroll
                for (int mi = 0; mi < 5; mi++)
                    mma_tf32(acc[mi][ni][0], acc[mi][ni][1],
                             acc[mi][ni][2], acc[mi][ni][3],
                             Af[mi][0], Af[mi][1], Af[mi][2], Af[mi][3],
                             b0, b1);
            }
        }

        if (it < 9) {                         // convert prefetched F -> D
            float* dst = sB + (buf ^ 1) * 16 * SB_P;
#pragma unroll
            for (int j = 0; j < 5; j++) {
                float2 r;
                r.x = lrelu(f0*p0[j].x + f1*p1[j].x + f2*p2[j].x + f3*p3[j].x);
                r.y = lrelu(f0*p0[j].y + f1*p1[j].y + f2*p2[j].y + f3*p3[j].y);
                *(float2*)&dst[dk[j] * SB_P + dw[j]] = r;
            }
        }
        __syncthreads();
        buf ^= 1;
    }

    float* Eb = g_E + ((size_t)(b * C_ + c)) * HW_;
#pragma unroll
    for (int mi = 0; mi < 5; mi++) {
        int r0 = mw0 + mi * 16 + qr;
#pragma unroll
        for (int ni = 0; ni < 5; ni++) {
            int col = nw0 + ni * 8 + 2 * qc;
            *(float2*)&Eb[r0 * W_ + col]       = make_float2(acc[mi][ni][0], acc[mi][ni][1]);
            *(float2*)&Eb[(r0 + 8) * W_ + col] = make_float2(acc[mi][ni][2], acc[mi][ni][3]);
        }
    }
}

// ---------------- k6: out = W_e @ E + x, TF32 MMA, both streamed ----------
// tile 256(o) x 80(p); 8 warps 4x2; warp 64x40; K chunk 16; 3-stage ring;
// ONE barrier per iteration; 2 CTAs/SM.
#define WP6 20             // sW pitch [256][20]: bank(20*qr+qc) all distinct
#define EP6 104            // sE pitch [16][104]: 104%32=8 -> conflict-free
#define K6_STG ((256*WP6 + 16*EP6))
#define K6_SMEM (3*K6_STG*4)
__global__ void __launch_bounds__(256, 2)
k6_out(const float* __restrict__ w_e,
       const float* __restrict__ x,
       float* __restrict__ out) {
    extern __shared__ float sm6[];

    const int pb = blockIdx.x;     // 0..319
    const int b  = blockIdx.y;

    const int tid  = threadIdx.x;
    const int wid  = tid >> 5;
    const int lane = tid & 31;
    const int qr   = lane >> 2;
    const int qc   = lane & 3;
    const int mw0  = (wid & 3) * 64;     // warp M offset (o), 4 warps
    const int nw0  = (wid >> 2) * 40;    // warp N offset (p), 2 warps
    const int p0   = pb * 80;

    const float* Eb = g_E + (size_t)b * C_ * HW_ + p0;

    // stage chunk `ck` into ring slot `s`
    auto stage = [&](int s, int ck) {
        float* dW = sm6 + s * K6_STG;
        float* dE = dW + 256 * WP6;
        const int kc = ck * 16;
        // W: 256 rows x 4 16B units
        for (int t = tid; t < 1024; t += 256) {
            int row = t >> 2, seg = t & 3;
            cp_async16(dW + row * WP6 + seg * 4, w_e + row * C_ + kc + seg * 4);
        }
        // E: 16 rows x 20 16B units = 320
        for (int t = tid; t < 320; t += 256) {
            int row = t / 20, seg = t - row * 20;
            cp_async16(dE + row * EP6 + seg * 4,
                       Eb + (size_t)(kc + row) * HW_ + seg * 4);
        }
        cp_commit();
    };

    stage(0, 0);
    stage(1, 1);

    float acc[4][5][4];
#pragma unroll
    for (int i = 0; i < 4; i++)
#pragma unroll
        for (int j = 0; j < 5; j++)
#pragma unroll
            for (int q = 0; q < 4; q++) acc[i][j][q] = 0.0f;

    for (int it = 0; it < 16; it++) {
        if (it < 15) cp_wait<1>();   // chunk `it` landed; it+1 may be in flight
        else         cp_wait<0>();
        __syncthreads();             // data visible; prev compute on slot done
        if (it < 14) stage((it + 2) % 3, it + 2);

        const float* sW = sm6 + (it % 3) * K6_STG;
        const float* sE = sW + 256 * WP6;

#pragma unroll
        for (int kk = 0; kk < 16; kk += 8) {
            float Af[4][4];
#pragma unroll
            for (int mi = 0; mi < 4; mi++) {
                int m0 = mw0 + mi * 16;
                const float* ar = sW + kk + qc;
                Af[mi][0] = ar[(m0 + qr)     * WP6];
                Af[mi][1] = ar[(m0 + qr + 8) * WP6];
                Af[mi][2] = ar[(m0 + qr)     * WP6 + 4];
                Af[mi][3] = ar[(m0 + qr + 8) * WP6 + 4];
            }
#pragma unroll
            for (int ni = 0; ni < 5; ni++) {
                int n0 = nw0 + ni * 8;
                float b0 = sE[(kk + qc)     * EP6 + n0 + qr];
                float b1 = sE[(kk + qc + 4) * EP6 + n0 + qr];
#pragma unroll
                for (int mi = 0; mi < 4; mi++)
                    mma_tf32(acc[mi][ni][0], acc[mi][ni][1],
                             acc[mi][ni][2], acc[mi][ni][3],
                             Af[mi][0], Af[mi][1], Af[mi][2], Af[mi][3],
                             b0, b1);
            }
        }
    }

    const float* xb  = x   + (size_t)b * C_ * HW_ + p0;
    float*       obp = out + (size_t)b * C_ * HW_ + p0;
#pragma unroll
    for (int mi = 0; mi < 4; mi++) {
        int o = mw0 + mi * 16 + qr;
#pragma unroll
        for (int ni = 0; ni < 5; ni++) {
            int col = nw0 + ni * 8 + 2 * qc;
            {
                float2 xv = *(const float2*)&xb[(size_t)o * HW_ + col];
                *(float2*)&obp[(size_t)o * HW_ + col] =
                    make_float2(acc[mi][ni][0] + xv.x, acc[mi][ni][1] + xv.y);
            }
            {
                float2 xv = *(const float2*)&xb[(size_t)(o + 8) * HW_ + col];
                *(float2*)&obp[(size_t)(o + 8) * HW_ + col] =
                    make_float2(acc[mi][ni][2] + xv.x, acc[mi][ni][3] + xv.y);
            }
        }
    }
}

// ---------------- launch --------------------------------------------------
extern "C" void kernel_launch(void* const* d_in, const int* in_sizes, int n_in,
                              void* d_out, int out_size) {
    const float* x    = (const float*)d_in[0];
    const float* w1   = (const float*)d_in[1];
    const float* w3   = (const float*)d_in[2];
    const float* w5   = (const float*)d_in[3];
    const float* w7   = (const float*)d_in[4];
    const float* w_ab = (const float*)d_in[5];
    const float* w_fc = (const float*)d_in[6];
    const float* w_fd = (const float*)d_in[7];
    const float* w_e  = (const float*)d_in[8];
    float* out = (float*)d_out;

    cudaFuncSetAttribute(k5_E,   cudaFuncAttributeMaxDynamicSharedMemorySize, K5_SMEM);
    cudaFuncSetAttribute(k6_out, cudaFuncAttributeMaxDynamicSharedMemorySize, K6_SMEM);

    k1_reduce<<<dim3(HW_ / 1024, B_), 256>>>(x, w_ab);
    k2_convs <<<dim3(5, 5, B_), dim3(32, 32)>>>(w1, w3, w5, w7, w_fc);
    k3_attn  <<<dim3(H_, B_), 256>>>();
    k5_E     <<<dim3(C_, B_), 256, K5_SMEM>>>(w_fd);
    k6_out   <<<dim3(320, B_), 256, K6_SMEM>>>(w_e, x, out);
}